// round 12
// baseline (speedup 1.0000x reference)
#include <cuda_runtime.h>
#include <cuda_bf16.h>
#include <cstdint>
#include <math.h>

#define N_RAYS 262144
#define HASHMAP_SIZE 524288
#define HMASK 0x7FFFFu
#define DIM 256
#define N_MID 6
#define PRIME1 2654435761u

#define TILE_M 32
#define THREADS 128
#define NCTAS (N_RAYS / TILE_M)       // 8192
#define SA_B 528                      // A row stride bytes (264 bf16): conflict-free ldmatrix
#define ABUF_B (TILE_M * SA_B)        // 16896
#define AHI_OFF 0
#define ALO_OFF ABUF_B
#define BIAS_OFF (2 * ABUF_B)               // 33792
#define WOUT_OFF (BIAS_OFF + 7 * 256 * 4)   // 40960
#define PART_OFF (WOUT_OFF + 1024)          // 41984
#define SMEM_TOTAL (PART_OFF + 128)         // 42112

// fragment-packed weights: uint2 = {b0,b1} regs of mma.m16n8k16 B operand
// mid: [l(6)][kt(16)][nt(32)][lane(32)] ; in: [nt(32)][lane(32)]
#define PKM_PER_LAYER (16 * 32 * 32)        // 16384
__device__ uint2 g_pkm_hi[N_MID * PKM_PER_LAYER];
__device__ uint2 g_pkm_lo[N_MID * PKM_PER_LAYER];
__device__ uint2 g_pki_hi[32 * 32];
__device__ uint2 g_pki_lo[32 * 32];

__device__ __forceinline__ uint32_t smem_u32(const void* p) {
    uint32_t a;
    asm("{ .reg .u64 t; cvta.to.shared.u64 t, %1; cvt.u32.u64 %0, t; }" : "=r"(a) : "l"(p));
    return a;
}
__device__ __forceinline__ uint32_t pack_bf2(__nv_bfloat16 a, __nv_bfloat16 b) {
    return (uint32_t)__bfloat16_as_ushort(a) | ((uint32_t)__bfloat16_as_ushort(b) << 16);
}
__device__ __forceinline__ void split_bf(float v, __nv_bfloat16& h, __nv_bfloat16& l) {
    h = __float2bfloat16(v);
    l = __float2bfloat16(v - __bfloat162float(h));
}

#define MMA(d, a, b0v, b1v) \
    asm volatile("mma.sync.aligned.m16n8k16.row.col.f32.bf16.bf16.f32 " \
        "{%0,%1,%2,%3},{%4,%5,%6,%7},{%8,%9},{%0,%1,%2,%3};" \
        : "+f"((d)[0]), "+f"((d)[1]), "+f"((d)[2]), "+f"((d)[3]) \
        : "r"((a)[0]), "r"((a)[1]), "r"((a)[2]), "r"((a)[3]), "r"(b0v), "r"(b1v))

#define LDSM4(r, addr) \
    asm volatile("ldmatrix.sync.aligned.m8n8.x4.shared.b16 {%0,%1,%2,%3}, [%4];" \
        : "=r"((r)[0]), "=r"((r)[1]), "=r"((r)[2]), "=r"((r)[3]) : "r"(addr))

// ---------------- weight prep: fp32 -> per-thread MMA fragments (bf16 hi/lo) ----------------
#define PREP_MID (N_MID * PKM_PER_LAYER)    // 98304
#define PREP_TOT (PREP_MID + 1024)
__global__ __launch_bounds__(256) void prep_kernel(
    const float* __restrict__ Wmid, const float* __restrict__ Win)
{
    int idx = blockIdx.x * 256 + threadIdx.x;
    if (idx >= PREP_TOT) return;
    const float* W;
    int t, nt, k0base, out_idx;
    bool is_in = idx >= PREP_MID;
    if (is_in) {
        int i2 = idx - PREP_MID;
        t = i2 & 31; nt = (i2 >> 5) & 31;
        k0base = 0; W = Win; out_idx = i2;
    } else {
        t = idx & 31; nt = (idx >> 5) & 31;
        int kt = (idx >> 10) & 15; int l = idx >> 14;
        k0base = kt * 16; W = Wmid + (size_t)l * DIM * DIM; out_idx = idx;
    }
    int n = nt * 8 + (t >> 2);
    int k0 = k0base + (t & 3) * 2;
    float w00 = W[(size_t)k0 * DIM + n];
    float w01 = W[(size_t)(k0 + 1) * DIM + n];
    float w10 = W[(size_t)(k0 + 8) * DIM + n];
    float w11 = W[(size_t)(k0 + 9) * DIM + n];
    uint2 hi, lo;
    __nv_bfloat16 h0, l0, h1, l1;
    split_bf(w00, h0, l0); split_bf(w01, h1, l1);
    hi.x = pack_bf2(h0, h1); lo.x = pack_bf2(l0, l1);
    split_bf(w10, h0, l0); split_bf(w11, h1, l1);
    hi.y = pack_bf2(h0, h1); lo.y = pack_bf2(l0, l1);
    if (is_in) { g_pki_hi[out_idx] = hi; g_pki_lo[out_idx] = lo; }
    else       { g_pkm_hi[out_idx] = hi; g_pkm_lo[out_idx] = lo; }
}

// ---------------- one K=16 step: 3-term split MMA, 2 m-tiles x 8 n-tiles ----------------
__device__ __forceinline__ void do_kt(
    uint32_t kt_boff, const uint2* __restrict__ pp_hi, const uint2* __restrict__ pp_lo,
    uint32_t smAhi, uint32_t a_lane_off, float (&acc)[2][8][4])
{
    uint2 bh[8], bl[8];
#pragma unroll
    for (int j = 0; j < 8; j++) { bh[j] = pp_hi[j * 32]; bl[j] = pp_lo[j * 32]; }
    uint32_t ah[2][4], al[2][4];
#pragma unroll
    for (int mm = 0; mm < 2; mm++) {
        uint32_t addr = smAhi + a_lane_off + (uint32_t)mm * (16 * SA_B) + kt_boff;
        LDSM4(ah[mm], addr);
        LDSM4(al[mm], addr + ABUF_B);
    }
#pragma unroll
    for (int mm = 0; mm < 2; mm++)
#pragma unroll
        for (int j = 0; j < 8; j++) MMA(acc[mm][j], ah[mm], bh[j].x, bh[j].y);
#pragma unroll
    for (int mm = 0; mm < 2; mm++)
#pragma unroll
        for (int j = 0; j < 8; j++) MMA(acc[mm][j], ah[mm], bl[j].x, bl[j].y);
#pragma unroll
    for (int mm = 0; mm < 2; mm++)
#pragma unroll
        for (int j = 0; j < 8; j++) MMA(acc[mm][j], al[mm], bh[j].x, bh[j].y);
}

// ---------------- fused model ----------------
__global__ __launch_bounds__(THREADS, 4) void fused_kernel(
    const float* __restrict__ x,
    const float* __restrict__ t1,
    const float* __restrict__ t2,
    const float* __restrict__ b_in,
    const float* __restrict__ b_mid,
    const float* __restrict__ W_out,
    const float* __restrict__ b_out,
    float* __restrict__ out,
    int4 res)
{
    extern __shared__ char smem[];
    float* sbias = (float*)(smem + BIAS_OFF);
    float* swout = (float*)(smem + WOUT_OFF);
    float* spart = (float*)(smem + PART_OFF);
    int tid = threadIdx.x;
    int w = tid >> 5;
    int t = tid & 31;

    // prologue: biases (7*256), wout, partial init
#pragma unroll
    for (int i = tid; i < 7 * 256; i += THREADS)
        sbias[i] = (i < 256) ? b_in[i] : b_mid[i - 256];
#pragma unroll
    for (int i = tid; i < 256; i += THREADS) swout[i] = W_out[i];
    if (tid < TILE_M) spart[tid] = 0.0f;

    // encode: threads 0-31 -> row tid of A buffers (cols 0-15)
    if (tid < TILE_M) {
        int ray = blockIdx.x * TILE_M + tid;
        float4 xv = ((const float4*)x)[ray];
        int rs[4] = {res.x, res.y, res.z, res.w};
        float e[16];
#pragma unroll
        for (int enc = 0; enc < 2; enc++) {
            float px = enc ? xv.z : xv.x;
            float py = enc ? xv.w : xv.y;
            const float* tab = enc ? t2 : t1;
#pragma unroll
            for (int l = 0; l < 4; l++) {
                float r = (float)rs[l];
                float xf0 = px * r, xf1 = py * r;
                float xi0 = floorf(xf0), xi1 = floorf(xf1);
                float fx = xf0 - xi0, fy = xf1 - xi1;
                unsigned u0 = (unsigned)xi0, u1 = (unsigned)xi1;
                const float2* T = (const float2*)(tab + (size_t)l * HASHMAP_SIZE * 2);
                unsigned b0 = u1 * PRIME1, b1 = (u1 + 1u) * PRIME1;
                float2 v00 = T[(u0 ^ b0) & HMASK];
                float2 v01 = T[(u0 ^ b1) & HMASK];
                float2 v10 = T[((u0 + 1u) ^ b0) & HMASK];
                float2 v11 = T[((u0 + 1u) ^ b1) & HMASK];
                float w00 = (1.f - fx) * (1.f - fy), w01 = (1.f - fx) * fy;
                float w10 = fx * (1.f - fy), w11 = fx * fy;
                e[enc * 8 + l * 2 + 0] = w00 * v00.x + w01 * v01.x + w10 * v10.x + w11 * v11.x;
                e[enc * 8 + l * 2 + 1] = w00 * v00.y + w01 * v01.y + w10 * v10.y + w11 * v11.y;
            }
        }
        uint32_t* rh = (uint32_t*)(smem + AHI_OFF + tid * SA_B);
        uint32_t* rl = (uint32_t*)(smem + ALO_OFF + tid * SA_B);
#pragma unroll
        for (int j = 0; j < 8; j++) {
            __nv_bfloat16 h0, l0, h1, l1;
            split_bf(e[2 * j], h0, l0);
            split_bf(e[2 * j + 1], h1, l1);
            rh[j] = pack_bf2(h0, h1);
            rl[j] = pack_bf2(l0, l1);
        }
    }
    __syncthreads();

    uint32_t smAhi = smem_u32(smem);
    uint32_t a_lane_off = (uint32_t)(t & 15) * SA_B + (uint32_t)(t >> 4) * 16;

    float acc[2][8][4];

    for (int g = 0; g < 7; g++) {
#pragma unroll
        for (int m = 0; m < 2; m++)
#pragma unroll
            for (int j = 0; j < 8; j++)
#pragma unroll
                for (int q = 0; q < 4; q++) acc[m][j][q] = 0.0f;

        if (g == 0) {
            do_kt(0, g_pki_hi + w * 256 + t, g_pki_lo + w * 256 + t, smAhi, a_lane_off, acc);
        } else {
            const uint2* bh = g_pkm_hi + (size_t)(g - 1) * PKM_PER_LAYER + w * 256 + t;
            const uint2* bl = g_pkm_lo + (size_t)(g - 1) * PKM_PER_LAYER + w * 256 + t;
#pragma unroll 1
            for (int kt = 0; kt < 16; kt++)
                do_kt((uint32_t)kt * 32, bh + kt * 1024, bl + kt * 1024, smAhi, a_lane_off, acc);
        }
        __syncthreads();   // all warps done reading A

        if (g < 6) {
            const float* bs = sbias + g * 256;
#pragma unroll
            for (int m = 0; m < 2; m++) {
#pragma unroll
                for (int j = 0; j < 8; j++) {
                    int r0 = m * 16 + (t >> 2);
                    int c0 = w * 64 + j * 8 + (t & 3) * 2;
                    float v0 = fmaxf(acc[m][j][0] + bs[c0], 0.0f);
                    float v1 = fmaxf(acc[m][j][1] + bs[c0 + 1], 0.0f);
                    float v2 = fmaxf(acc[m][j][2] + bs[c0], 0.0f);
                    float v3 = fmaxf(acc[m][j][3] + bs[c0 + 1], 0.0f);
                    __nv_bfloat16 h0, l0, h1, l1;
                    split_bf(v0, h0, l0); split_bf(v1, h1, l1);
                    *(uint32_t*)(smem + AHI_OFF + r0 * SA_B + c0 * 2) = pack_bf2(h0, h1);
                    *(uint32_t*)(smem + ALO_OFF + r0 * SA_B + c0 * 2) = pack_bf2(l0, l1);
                    split_bf(v2, h0, l0); split_bf(v3, h1, l1);
                    *(uint32_t*)(smem + AHI_OFF + (r0 + 8) * SA_B + c0 * 2) = pack_bf2(h0, h1);
                    *(uint32_t*)(smem + ALO_OFF + (r0 + 8) * SA_B + c0 * 2) = pack_bf2(l0, l1);
                }
            }
            __syncthreads();
        } else {
            // output head: relu(D + b_mid[5]) . W_out + b_out
            const float* bs = sbias + 6 * 256;
#pragma unroll
            for (int m = 0; m < 2; m++) {
                float s0 = 0.0f, s1 = 0.0f;
#pragma unroll
                for (int j = 0; j < 8; j++) {
                    int c0 = w * 64 + j * 8 + (t & 3) * 2;
                    s0 += fmaxf(acc[m][j][0] + bs[c0], 0.0f) * swout[c0]
                        + fmaxf(acc[m][j][1] + bs[c0 + 1], 0.0f) * swout[c0 + 1];
                    s1 += fmaxf(acc[m][j][2] + bs[c0], 0.0f) * swout[c0]
                        + fmaxf(acc[m][j][3] + bs[c0 + 1], 0.0f) * swout[c0 + 1];
                }
                s0 += __shfl_xor_sync(0xFFFFFFFFu, s0, 1);
                s0 += __shfl_xor_sync(0xFFFFFFFFu, s0, 2);
                s1 += __shfl_xor_sync(0xFFFFFFFFu, s1, 1);
                s1 += __shfl_xor_sync(0xFFFFFFFFu, s1, 2);
                if ((t & 3) == 0) {
                    atomicAdd(&spart[m * 16 + (t >> 2)], s0);
                    atomicAdd(&spart[m * 16 + (t >> 2) + 8], s1);
                }
            }
            __syncthreads();
            if (tid < TILE_M)
                out[blockIdx.x * TILE_M + tid] = spart[tid] + b_out[0];
        }
    }
}

// ---------------- launch ----------------
extern "C" void kernel_launch(void* const* d_in, const int* in_sizes, int n_in,
                              void* d_out, int out_size)
{
    const float* x      = (const float*)d_in[0];
    const float* table1 = (const float*)d_in[1];
    const float* table2 = (const float*)d_in[2];
    const float* W_in   = (const float*)d_in[3];
    const float* b_in   = (const float*)d_in[4];
    const float* W_mid  = (const float*)d_in[5];
    const float* b_mid  = (const float*)d_in[6];
    const float* W_out  = (const float*)d_in[7];
    const float* b_out  = (const float*)d_in[8];
    float* out = (float*)d_out;

    // Replicate Python's RESOLUTIONS exactly (host libm, double precision).
    double bgrow = exp((log(512.0) - log(16.0)) / 3.0);
    int r[4];
    for (int l = 0; l < 4; l++) r[l] = (int)floor(16.0 * pow(bgrow, (double)l));
    int4 res = make_int4(r[0], r[1], r[2], r[3]);

    static bool attr_done = false;
    if (!attr_done) {
        cudaFuncSetAttribute(fused_kernel, cudaFuncAttributeMaxDynamicSharedMemorySize, SMEM_TOTAL);
        attr_done = true;
    }

    prep_kernel<<<(PREP_TOT + 255) / 256, 256>>>(W_mid, W_in);
    fused_kernel<<<NCTAS, THREADS, SMEM_TOTAL>>>(
        x, table1, table2, b_in, b_mid, W_out, b_out, out, res);
}

// round 16
// speedup vs baseline: 1.0048x; 1.0048x over previous
#include <cuda_runtime.h>
#include <cuda_bf16.h>
#include <cstdint>
#include <math.h>

#define N_RAYS 262144
#define HASHMAP_SIZE 524288
#define HMASK 0x7FFFFu
#define DIM 256
#define N_MID 6
#define PRIME1 2654435761u

#define TILE_M 32
#define THREADS 128
#define NCTAS (N_RAYS / TILE_M)       // 8192
#define SA_B 528                      // A row stride bytes (264 bf16): conflict-free ldmatrix
#define ABUF_B (TILE_M * SA_B)        // 16896
#define AHI_OFF 0
#define ALO_OFF ABUF_B
#define BIAS_OFF (2 * ABUF_B)               // 33792
#define WOUT_OFF (BIAS_OFF + 7 * 256 * 4)   // 40960
#define PART_OFF (WOUT_OFF + 1024)          // 41984
#define SMEM_TOTAL (PART_OFF + 128)         // 42112

// fragment-packed weights: uint2 = {b0,b1} regs of mma.m16n8k16 B operand
// mid: [l(6)][kt(16)][nt(32)][lane(32)] ; in: [nt(32)][lane(32)]
#define PKM_PER_LAYER (16 * 32 * 32)        // 16384
__device__ uint2 g_pkm_hi[N_MID * PKM_PER_LAYER];
__device__ uint2 g_pkm_lo[N_MID * PKM_PER_LAYER];
__device__ uint2 g_pki_hi[32 * 32];
__device__ uint2 g_pki_lo[32 * 32];

__device__ __forceinline__ uint32_t smem_u32(const void* p) {
    uint32_t a;
    asm("{ .reg .u64 t; cvta.to.shared.u64 t, %1; cvt.u32.u64 %0, t; }" : "=r"(a) : "l"(p));
    return a;
}
__device__ __forceinline__ uint32_t pack_bf2(__nv_bfloat16 a, __nv_bfloat16 b) {
    return (uint32_t)__bfloat16_as_ushort(a) | ((uint32_t)__bfloat16_as_ushort(b) << 16);
}
__device__ __forceinline__ void split_bf(float v, __nv_bfloat16& h, __nv_bfloat16& l) {
    h = __float2bfloat16(v);
    l = __float2bfloat16(v - __bfloat162float(h));
}
// fast truncation split of a pair: hi = top-16-bits (1 PRMT), lo = rn(residual) (1 CVT.BF16X2)
__device__ __forceinline__ void split2(float v0, float v1, uint32_t& hp, uint32_t& lp) {
    uint32_t u0 = __float_as_uint(v0), u1 = __float_as_uint(v1);
    hp = __byte_perm(u0, u1, 0x7632);
    float r0 = v0 - __uint_as_float(u0 & 0xFFFF0000u);
    float r1 = v1 - __uint_as_float(u1 & 0xFFFF0000u);
    asm("cvt.rn.bf16x2.f32 %0, %1, %2;" : "=r"(lp) : "f"(r1), "f"(r0));
}

#define MMA(d, a, b0v, b1v) \
    asm volatile("mma.sync.aligned.m16n8k16.row.col.f32.bf16.bf16.f32 " \
        "{%0,%1,%2,%3},{%4,%5,%6,%7},{%8,%9},{%0,%1,%2,%3};" \
        : "+f"((d)[0]), "+f"((d)[1]), "+f"((d)[2]), "+f"((d)[3]) \
        : "r"((a)[0]), "r"((a)[1]), "r"((a)[2]), "r"((a)[3]), "r"(b0v), "r"(b1v))

#define LDSM4(r, addr) \
    asm volatile("ldmatrix.sync.aligned.m8n8.x4.shared.b16 {%0,%1,%2,%3}, [%4];" \
        : "=r"((r)[0]), "=r"((r)[1]), "=r"((r)[2]), "=r"((r)[3]) : "r"(addr))

// ---------------- weight prep: fp32 -> per-thread MMA fragments (bf16 hi/lo) ----------------
#define PREP_MID (N_MID * PKM_PER_LAYER)    // 98304
#define PREP_TOT (PREP_MID + 1024)
__global__ __launch_bounds__(256) void prep_kernel(
    const float* __restrict__ Wmid, const float* __restrict__ Win)
{
    int idx = blockIdx.x * 256 + threadIdx.x;
    if (idx >= PREP_TOT) return;
    const float* W;
    int t, nt, k0base, out_idx;
    bool is_in = idx >= PREP_MID;
    if (is_in) {
        int i2 = idx - PREP_MID;
        t = i2 & 31; nt = (i2 >> 5) & 31;
        k0base = 0; W = Win; out_idx = i2;
    } else {
        t = idx & 31; nt = (idx >> 5) & 31;
        int kt = (idx >> 10) & 15; int l = idx >> 14;
        k0base = kt * 16; W = Wmid + (size_t)l * DIM * DIM; out_idx = idx;
    }
    int n = nt * 8 + (t >> 2);
    int k0 = k0base + (t & 3) * 2;
    float w00 = W[(size_t)k0 * DIM + n];
    float w01 = W[(size_t)(k0 + 1) * DIM + n];
    float w10 = W[(size_t)(k0 + 8) * DIM + n];
    float w11 = W[(size_t)(k0 + 9) * DIM + n];
    uint2 hi, lo;
    __nv_bfloat16 h0, l0, h1, l1;
    split_bf(w00, h0, l0); split_bf(w01, h1, l1);
    hi.x = pack_bf2(h0, h1); lo.x = pack_bf2(l0, l1);
    split_bf(w10, h0, l0); split_bf(w11, h1, l1);
    hi.y = pack_bf2(h0, h1); lo.y = pack_bf2(l0, l1);
    if (is_in) { g_pki_hi[out_idx] = hi; g_pki_lo[out_idx] = lo; }
    else       { g_pkm_hi[out_idx] = hi; g_pkm_lo[out_idx] = lo; }
}

// ---------------- one K=16 step: 3-term split MMA, 2 m-tiles x 8 n-tiles ----------------
__device__ __forceinline__ void do_kt(
    uint32_t kt_boff, const uint2* __restrict__ pp_hi, const uint2* __restrict__ pp_lo,
    uint32_t smAhi, uint32_t a_lane_off, float (&acc)[2][8][4])
{
    uint2 bh[8], bl[8];
#pragma unroll
    for (int j = 0; j < 8; j++) { bh[j] = pp_hi[j * 32]; bl[j] = pp_lo[j * 32]; }
    uint32_t ah[2][4], al[2][4];
#pragma unroll
    for (int mm = 0; mm < 2; mm++) {
        uint32_t addr = smAhi + a_lane_off + (uint32_t)mm * (16 * SA_B) + kt_boff;
        LDSM4(ah[mm], addr);
        LDSM4(al[mm], addr + ABUF_B);
    }
#pragma unroll
    for (int mm = 0; mm < 2; mm++)
#pragma unroll
        for (int j = 0; j < 8; j++) MMA(acc[mm][j], ah[mm], bh[j].x, bh[j].y);
#pragma unroll
    for (int mm = 0; mm < 2; mm++)
#pragma unroll
        for (int j = 0; j < 8; j++) MMA(acc[mm][j], ah[mm], bl[j].x, bl[j].y);
#pragma unroll
    for (int mm = 0; mm < 2; mm++)
#pragma unroll
        for (int j = 0; j < 8; j++) MMA(acc[mm][j], al[mm], bh[j].x, bh[j].y);
}

// ---------------- fused model ----------------
__global__ __launch_bounds__(THREADS, 4) void fused_kernel(
    const float* __restrict__ x,
    const float* __restrict__ t1,
    const float* __restrict__ t2,
    const float* __restrict__ b_in,
    const float* __restrict__ b_mid,
    const float* __restrict__ W_out,
    const float* __restrict__ b_out,
    float* __restrict__ out,
    int4 res)
{
    extern __shared__ char smem[];
    float* sbias = (float*)(smem + BIAS_OFF);
    float* swout = (float*)(smem + WOUT_OFF);
    float* spart = (float*)(smem + PART_OFF);
    int tid = threadIdx.x;
    int w = tid >> 5;
    int t = tid & 31;

    // prologue: biases (7*256), wout, partial init
#pragma unroll
    for (int i = tid; i < 7 * 256; i += THREADS)
        sbias[i] = (i < 256) ? b_in[i] : b_mid[i - 256];
#pragma unroll
    for (int i = tid; i < 256; i += THREADS) swout[i] = W_out[i];
    if (tid < TILE_M) spart[tid] = 0.0f;

    // encode: ALL 128 threads. 4 threads per ray; thread (ray, sub) computes
    // (enc = sub>>1), levels l = (2*sub)&3 and (2*sub+1)&3, i.e. slots 2*sub, 2*sub+1.
    // slot -> output uint32 index j = slot (cols 2j, 2j+1 of the A row).
    {
        int row = tid >> 2;
        int sub = tid & 3;
        int ray = blockIdx.x * TILE_M + row;
        float4 xv = ((const float4*)x)[ray];
        int enc = sub >> 1;
        float px = enc ? xv.z : xv.x;
        float py = enc ? xv.w : xv.y;
        const float* tab = enc ? t2 : t1;
        int rs[4] = {res.x, res.y, res.z, res.w};
        uint32_t* rh = (uint32_t*)(smem + AHI_OFF + row * SA_B);
        uint32_t* rl = (uint32_t*)(smem + ALO_OFF + row * SA_B);
#pragma unroll
        for (int i = 0; i < 2; i++) {
            int slot = sub * 2 + i;
            int l = slot & 3;
            float r = (float)rs[l];
            float xf0 = px * r, xf1 = py * r;
            float xi0 = floorf(xf0), xi1 = floorf(xf1);
            float fx = xf0 - xi0, fy = xf1 - xi1;
            unsigned u0 = (unsigned)xi0, u1 = (unsigned)xi1;
            const float2* T = (const float2*)(tab + (size_t)l * HASHMAP_SIZE * 2);
            unsigned b0 = u1 * PRIME1, b1 = (u1 + 1u) * PRIME1;
            float2 v00 = T[(u0 ^ b0) & HMASK];
            float2 v01 = T[(u0 ^ b1) & HMASK];
            float2 v10 = T[((u0 + 1u) ^ b0) & HMASK];
            float2 v11 = T[((u0 + 1u) ^ b1) & HMASK];
            float w00 = (1.f - fx) * (1.f - fy), w01 = (1.f - fx) * fy;
            float w10 = fx * (1.f - fy), w11 = fx * fy;
            float e0 = w00 * v00.x + w01 * v01.x + w10 * v10.x + w11 * v11.x;
            float e1 = w00 * v00.y + w01 * v01.y + w10 * v10.y + w11 * v11.y;
            uint32_t hp, lp;
            split2(e0, e1, hp, lp);
            rh[slot] = hp;
            rl[slot] = lp;
        }
    }
    __syncthreads();

    uint32_t smAhi = smem_u32(smem);
    uint32_t a_lane_off = (uint32_t)(t & 15) * SA_B + (uint32_t)(t >> 4) * 16;

    float acc[2][8][4];

    for (int g = 0; g < 7; g++) {
#pragma unroll
        for (int m = 0; m < 2; m++)
#pragma unroll
            for (int j = 0; j < 8; j++)
#pragma unroll
                for (int q = 0; q < 4; q++) acc[m][j][q] = 0.0f;

        if (g == 0) {
            do_kt(0, g_pki_hi + w * 256 + t, g_pki_lo + w * 256 + t, smAhi, a_lane_off, acc);
        } else {
            const uint2* bh = g_pkm_hi + (size_t)(g - 1) * PKM_PER_LAYER + w * 256 + t;
            const uint2* bl = g_pkm_lo + (size_t)(g - 1) * PKM_PER_LAYER + w * 256 + t;
#pragma unroll 1
            for (int kt = 0; kt < 16; kt++)
                do_kt((uint32_t)kt * 32, bh + kt * 1024, bl + kt * 1024, smAhi, a_lane_off, acc);
        }
        __syncthreads();   // all warps done reading A

        if (g < 6) {
            const float* bs = sbias + g * 256;
#pragma unroll
            for (int m = 0; m < 2; m++) {
#pragma unroll
                for (int j = 0; j < 8; j++) {
                    int r0 = m * 16 + (t >> 2);
                    int c0 = w * 64 + j * 8 + (t & 3) * 2;
                    float b0v = bs[c0], b1v = bs[c0 + 1];
                    float v0 = fmaxf(acc[m][j][0] + b0v, 0.0f);
                    float v1 = fmaxf(acc[m][j][1] + b1v, 0.0f);
                    float v2 = fmaxf(acc[m][j][2] + b0v, 0.0f);
                    float v3 = fmaxf(acc[m][j][3] + b1v, 0.0f);
                    uint32_t hp, lp;
                    split2(v0, v1, hp, lp);
                    *(uint32_t*)(smem + AHI_OFF + r0 * SA_B + c0 * 2) = hp;
                    *(uint32_t*)(smem + ALO_OFF + r0 * SA_B + c0 * 2) = lp;
                    split2(v2, v3, hp, lp);
                    *(uint32_t*)(smem + AHI_OFF + (r0 + 8) * SA_B + c0 * 2) = hp;
                    *(uint32_t*)(smem + ALO_OFF + (r0 + 8) * SA_B + c0 * 2) = lp;
                }
            }
            __syncthreads();
        } else {
            // output head: relu(D + b_mid[5]) . W_out + b_out
            const float* bs = sbias + 6 * 256;
#pragma unroll
            for (int m = 0; m < 2; m++) {
                float s0 = 0.0f, s1 = 0.0f;
#pragma unroll
                for (int j = 0; j < 8; j++) {
                    int c0 = w * 64 + j * 8 + (t & 3) * 2;
                    s0 += fmaxf(acc[m][j][0] + bs[c0], 0.0f) * swout[c0]
                        + fmaxf(acc[m][j][1] + bs[c0 + 1], 0.0f) * swout[c0 + 1];
                    s1 += fmaxf(acc[m][j][2] + bs[c0], 0.0f) * swout[c0]
                        + fmaxf(acc[m][j][3] + bs[c0 + 1], 0.0f) * swout[c0 + 1];
                }
                s0 += __shfl_xor_sync(0xFFFFFFFFu, s0, 1);
                s0 += __shfl_xor_sync(0xFFFFFFFFu, s0, 2);
                s1 += __shfl_xor_sync(0xFFFFFFFFu, s1, 1);
                s1 += __shfl_xor_sync(0xFFFFFFFFu, s1, 2);
                if ((t & 3) == 0) {
                    atomicAdd(&spart[m * 16 + (t >> 2)], s0);
                    atomicAdd(&spart[m * 16 + (t >> 2) + 8], s1);
                }
            }
            __syncthreads();
            if (tid < TILE_M)
                out[blockIdx.x * TILE_M + tid] = spart[tid] + b_out[0];
        }
    }
}

// ---------------- launch ----------------
extern "C" void kernel_launch(void* const* d_in, const int* in_sizes, int n_in,
                              void* d_out, int out_size)
{
    const float* x      = (const float*)d_in[0];
    const float* table1 = (const float*)d_in[1];
    const float* table2 = (const float*)d_in[2];
    const float* W_in   = (const float*)d_in[3];
    const float* b_in   = (const float*)d_in[4];
    const float* W_mid  = (const float*)d_in[5];
    const float* b_mid  = (const float*)d_in[6];
    const float* W_out  = (const float*)d_in[7];
    const float* b_out  = (const float*)d_in[8];
    float* out = (float*)d_out;

    // Replicate Python's RESOLUTIONS exactly (host libm, double precision).
    double bgrow = exp((log(512.0) - log(16.0)) / 3.0);
    int r[4];
    for (int l = 0; l < 4; l++) r[l] = (int)floor(16.0 * pow(bgrow, (double)l));
    int4 res = make_int4(r[0], r[1], r[2], r[3]);

    static bool attr_done = false;
    if (!attr_done) {
        cudaFuncSetAttribute(fused_kernel, cudaFuncAttributeMaxDynamicSharedMemorySize, SMEM_TOTAL);
        attr_done = true;
    }

    prep_kernel<<<(PREP_TOT + 255) / 256, 256>>>(W_mid, W_in);
    fused_kernel<<<NCTAS, THREADS, SMEM_TOTAL>>>(
        x, table1, table2, b_in, b_mid, W_out, b_out, out, res);
}